// round 16
// baseline (speedup 1.0000x reference)
#include <cuda_runtime.h>
#include <cstdint>

#define CHAR_VOCAB 1001
#define EMB 256
#define H 192
#define G3 576   // 3*H
#define BATCH 32
#define SEQL 2048
#define NSPAN 512

// cluster split
#define JH 96            // outputs per CTA
#define KS 4             // K-split ways
#define KC 48            // K per slice
#define NTHR (JH * KS)   // 384 threads

// ---------------- scratch (no cudaMalloc allowed) ----------------
__device__ float g_proj[2][CHAR_VOCAB * G3];                 // 2 x 2.3 MB
__device__ float g_allh[(size_t)BATCH * SEQL * 2 * H];       // 100.7 MB

// ---------------- kernel 1: proj tables (unchanged, verified) ----------------
#define VB 16
__global__ void proj_kernel(const float* __restrict__ emb,
                            const float* __restrict__ w_ih_f, const float* __restrict__ b_ih_f,
                            const float* __restrict__ w_ih_b, const float* __restrict__ b_ih_b) {
    __shared__ float embs[VB][EMB];
    const int dir = blockIdx.y;
    const float* __restrict__ w  = dir ? w_ih_b : w_ih_f;
    const float* __restrict__ bi = dir ? b_ih_b : b_ih_f;
    const int v0 = blockIdx.x * VB;

    for (int i = threadIdx.x; i < VB * EMB; i += blockDim.x) {
        int v = v0 + i / EMB;
        embs[i / EMB][i % EMB] = (v < CHAR_VOCAB) ? emb[(size_t)v * EMB + (i % EMB)] : 0.f;
    }
    __syncthreads();

    const int g = threadIdx.x;  // 0..575
    float acc[VB];
#pragma unroll
    for (int i = 0; i < VB; i++) acc[i] = 0.f;

    const float4* __restrict__ w4 = (const float4*)(w + (size_t)g * EMB);
    for (int e4 = 0; e4 < EMB / 4; e4++) {
        float4 wv = w4[e4];
#pragma unroll
        for (int i = 0; i < VB; i++) {
            float4 ev = *(const float4*)&embs[i][e4 * 4];
            acc[i] = fmaf(wv.x, ev.x, fmaf(wv.y, ev.y, fmaf(wv.z, ev.z, fmaf(wv.w, ev.w, acc[i]))));
        }
    }
    float bb = bi[g];
#pragma unroll
    for (int i = 0; i < VB; i++) {
        int v = v0 + i;
        if (v < CHAR_VOCAB) g_proj[dir][(size_t)v * G3 + g] = acc[i] + bb;
    }
}

// ---------------- PTX helpers ----------------
__device__ __forceinline__ uint32_t smem_u32(const void* p) {
    uint32_t a;
    asm("{ .reg .u64 t; cvta.to.shared.u64 t, %1; cvt.u32.u64 %0, t; }" : "=r"(a) : "l"(p));
    return a;
}
__device__ __forceinline__ uint32_t mapa_u32(uint32_t laddr, uint32_t peer) {
    uint32_t r;
    asm("mapa.shared::cluster.u32 %0, %1, %2;" : "=r"(r) : "r"(laddr), "r"(peer));
    return r;
}
__device__ __forceinline__ void st_remote_f32(uint32_t raddr, float v) {
    asm volatile("st.shared::cluster.b32 [%0], %1;" :: "r"(raddr), "r"(__float_as_uint(v)) : "memory");
}
// release-store of a sequence flag into the PEER's smem (cluster scope)
__device__ __forceinline__ void st_flag_release(uint32_t raddr, uint32_t v) {
    asm volatile("st.release.cluster.shared::cluster.b32 [%0], %1;" :: "r"(raddr), "r"(v) : "memory");
}
// acquire-load poll of a LOCAL smem flag until flag >= target.
// Monotonic sequence numbers: producer run-ahead makes this pass immediately —
// no parity aliasing, no deadlock window (unlike mbarrier parity waits).
__device__ __forceinline__ void wait_flag(uint32_t laddr, uint32_t target) {
    uint32_t v;
    do {
        asm volatile("ld.acquire.cluster.shared::cta.b32 %0, [%1];"
                     : "=r"(v) : "r"(laddr) : "memory");
    } while ((int)v < (int)target);
}
__device__ __forceinline__ void cluster_barrier() {
    asm volatile("barrier.cluster.arrive.aligned;" ::: "memory");
    asm volatile("barrier.cluster.wait.aligned;" ::: "memory");
}

// single-MUFU tanh; sigmoid(x) = 0.5 + 0.5*tanh(x/2)
__device__ __forceinline__ float tanh_apx(float x) {
    float y; asm("tanh.approx.f32 %0, %1;" : "=f"(y) : "f"(x)); return y;
}
__device__ __forceinline__ float sig_apx(float x) {
    return fmaf(0.5f, tanh_apx(0.5f * x), 0.5f);
}
__device__ __forceinline__ uint32_t bf16rn(float f) {
    uint32_t u = __float_as_uint(f);
    return (u + 0x7FFFu + ((u >> 16) & 1u)) >> 16;
}

// one dual-MAC on a packed bf16 pair (known-good regalloc form)
#define DOT2(a0, a1, w, hx, hy) { \
    float wl = __uint_as_float((w) << 16); \
    float wh = __uint_as_float((w) & 0xFFFF0000u); \
    a0 = fmaf(wl, (hx), a0); a1 = fmaf(wh, (hy), a1); }

// 3-gate dot over this thread's 48-element K slice
__device__ __forceinline__ void dot3(const float* __restrict__ hb,
                                     const uint32_t wv[3][24],
                                     float& sR, float& sZ, float& sN) {
    float aR0 = 0.f, aR1 = 0.f, aZ0 = 0.f, aZ1 = 0.f, aN0 = 0.f, aN1 = 0.f;
#pragma unroll
    for (int q = 0; q < 12; q++) {
        float4 h4 = *(const float4*)(hb + 4 * q);
        DOT2(aR0, aR1, wv[0][2 * q],     h4.x, h4.y);
        DOT2(aR0, aR1, wv[0][2 * q + 1], h4.z, h4.w);
        DOT2(aZ0, aZ1, wv[1][2 * q],     h4.x, h4.y);
        DOT2(aZ0, aZ1, wv[1][2 * q + 1], h4.z, h4.w);
        DOT2(aN0, aN1, wv[2][2 * q],     h4.x, h4.y);
        DOT2(aN0, aN1, wv[2][2 * q + 1], h4.z, h4.w);
    }
    sR = aR0 + aR1; sZ = aZ0 + aZ1; sN = aN0 + aN1;
}

// ---------------- kernel 2: clustered GRU, two batches, PIPELINED schedule ----
// cluster(2,1,1): rank r owns global j in [96r,96r+96) for BOTH batches; same
// warps serve both batches (same W slice in registers, 72 u32).
// Handoff: producer ks0 warps push h into peer smem, then elected lane does a
// release-store of flag[b][w] = s+1 (sequence number). Peer-half warps poll
// their LOCAL flags with acquire loads until >= s. Monotonic counters cannot
// alias across phases — the mbarrier parity double-advance deadlock is gone.
// Step: [waitA | dot_b0 | sync1 | ks0: epi_b0+push+flag] while others run
//       [waitB | dot_b1 | sync2 | ks0: epi_b1+push+flag] -> b0's DSMEM transit
// hides under dot_b1; b1's under loop-around + dot_b0.
__global__ void __launch_bounds__(NTHR, 1) __cluster_dims__(2, 1, 1)
gru_kernel(const int* __restrict__ char_ids,
           const float* __restrict__ w_hh_f, const float* __restrict__ b_hh_f,
           const float* __restrict__ w_hh_b, const float* __restrict__ b_hh_b) {
    __shared__ float hbuf[2][2][H];        // [batch][parity][H]
    __shared__ float part[2][2][9][JH];    // [batch][parity][(ks-1)*3+gate][jl]
    __shared__ int   ids_s[2][SEQL];
    __shared__ uint32_t flg[2][4];         // [batch][producer warp 0..2] (+pad)

    const int rank = blockIdx.x;
    const int dir  = blockIdx.y;
    const int bp   = blockIdx.z;           // batch pair 0..15
    const int b0   = 2 * bp, b1 = 2 * bp + 1;
    const float* __restrict__ whh = dir ? w_hh_b : w_hh_f;
    const float* __restrict__ bhh = dir ? b_hh_b : b_hh_f;
    const float* __restrict__ proj = g_proj[dir];

    const int tid = threadIdx.x;
    const int ks  = tid / JH;                 // 0..3 (uniform per warp)
    const int jl  = tid % JH;                 // 0..95
    const int jg  = rank * JH + jl;           // 0..191
    const int kslice = (ks + 2 * rank) & 3;   // ks<2 -> own half for BOTH ranks
    const bool own_half = (ks < 2);

    // ---- prologue ----
    if (tid < 8) ((uint32_t*)flg)[tid] = 0;    // flags = 0 (step-0 input = zeros)
    ((float*)hbuf)[tid] = 0.f;
    ((float*)hbuf)[NTHR + tid] = 0.f;          // zero all 768 floats
    for (int t = tid; t < SEQL; t += NTHR) {
        ids_s[0][t] = char_ids[(size_t)b0 * SEQL + t];
        ids_s[1][t] = char_ids[(size_t)b1 * SEQL + t];
    }
    // W_hh slice -> registers, packed bf16 pairs (shared by both batches)
    uint32_t wv[3][24];
#pragma unroll
    for (int g = 0; g < 3; g++) {
        const float2* __restrict__ wr2 =
            (const float2*)(whh + ((size_t)(g * H + jg)) * H + kslice * KC);
#pragma unroll
        for (int q = 0; q < 24; q++) {
            float2 f = wr2[q];
            wv[g][q] = bf16rn(f.x) | (bf16rn(f.y) << 16);
        }
    }
    __syncthreads();
    cluster_barrier();   // zeroed flags + hbuf visible cluster-wide

    const uint32_t peer = rank ^ 1;
    const int wrp = tid >> 5;                  // warp id; ks0 warps are 0,1,2
    // producer-side remote addresses (peer's flags for each batch, this warp)
    const uint32_t p_flg0 = mapa_u32(smem_u32(&flg[0][wrp & 3]), peer);
    const uint32_t p_flg1 = mapa_u32(smem_u32(&flg[1][wrp & 3]), peer);
    // consumer-side local flag addresses
    const uint32_t l_f00 = smem_u32(&flg[0][0]);
    const uint32_t l_f01 = smem_u32(&flg[0][1]);
    const uint32_t l_f02 = smem_u32(&flg[0][2]);
    const uint32_t l_f10 = smem_u32(&flg[1][0]);
    const uint32_t l_f11 = smem_u32(&flg[1][1]);
    const uint32_t l_f12 = smem_u32(&flg[1][2]);
    // producer-side remote h slots
    const uint32_t r_h00 = mapa_u32(smem_u32(&hbuf[0][0][jg]), peer);
    const uint32_t r_h01 = mapa_u32(smem_u32(&hbuf[0][1][jg]), peer);
    const uint32_t r_h10 = mapa_u32(smem_u32(&hbuf[1][0][jg]), peer);
    const uint32_t r_h11 = mapa_u32(smem_u32(&hbuf[1][1][jg]), peer);

    // ks0-only state (biases shared across batches — same direction)
    float bhr = 0.f, bhz = 0.f, bhn = 0.f;
    float h0 = 0.f, h1 = 0.f;
    float xr0 = 0.f, xz0 = 0.f, xn0 = 0.f, xr1 = 0.f, xz1 = 0.f, xn1 = 0.f;
    float* allh0 = g_allh + ((size_t)b0 * SEQL) * (2 * H) + dir * H + jg;
    float* allh1 = g_allh + ((size_t)b1 * SEQL) * (2 * H) + dir * H + jg;
    if (ks == 0) {
        bhr = bhh[jg]; bhz = bhh[H + jg]; bhn = bhh[2 * H + jg];
        int t0 = dir ? (SEQL - 1) : 0;
        const float* pa = proj + (size_t)ids_s[0][t0] * G3 + jg;
        xr0 = pa[0]; xz0 = pa[H]; xn0 = pa[2 * H];
        const float* pb = proj + (size_t)ids_s[1][t0] * G3 + jg;
        xr1 = pb[0]; xz1 = pb[H]; xn1 = pb[2 * H];
    }

#pragma unroll 1
    for (int s = 0; s < SEQL; s++) {
        const uint32_t par = (uint32_t)(s & 1);
        const int nxt = (s + 1) & 1;
        const int tcur = dir ? (SEQL - 1 - s) : s;
        const int sn = (s + 1 < SEQL) ? s + 1 : s;
        const int tn = dir ? (SEQL - 1 - sn) : sn;
        const uint32_t su = (uint32_t)s;

        // ================= phase A: batch 0 =================
        if (!own_half) {   // peer-half: need peer's step-(s-1) pushes (flag >= s)
            wait_flag(l_f00, su); wait_flag(l_f01, su); wait_flag(l_f02, su);
        }
        float xrN0 = 0.f, xzN0 = 0.f, xnN0 = 0.f;
        if (ks == 0) {
            const float* pn = proj + (size_t)ids_s[0][tn] * G3 + jg;
            xrN0 = __ldg(pn); xzN0 = __ldg(pn + H); xnN0 = __ldg(pn + 2 * H);
        }
        float sR0, sZ0, sN0;
        dot3(&hbuf[0][par][kslice * KC], wv, sR0, sZ0, sN0);
        if (ks != 0) {
            part[0][par][(ks - 1) * 3 + 0][jl] = sR0;
            part[0][par][(ks - 1) * 3 + 1][jl] = sZ0;
            part[0][par][(ks - 1) * 3 + 2][jl] = sN0;
        }
        __syncthreads();   // sync1 — b0 partials visible; hbuf[1][nxt](s-1) published

        if (ks == 0) {     // epilogue b0 runs while other warps start phase B
            float aR = sR0 + part[0][par][0][jl] + part[0][par][3][jl] + part[0][par][6][jl];
            float aZ = sZ0 + part[0][par][1][jl] + part[0][par][4][jl] + part[0][par][7][jl];
            float aN = sN0 + part[0][par][2][jl] + part[0][par][5][jl] + part[0][par][8][jl];
            float r = sig_apx(xr0 + bhr + aR);
            float z = sig_apx(xz0 + bhz + aZ);
            float n = tanh_apx(fmaf(r, aN + bhn, xn0));
            h0 = fmaf(z, h0 - n, n);
            hbuf[0][nxt][jg] = h0;
            st_remote_f32(par ? r_h00 : r_h01, h0);   // nxt buffer on peer
            allh0[(size_t)tcur * (2 * H)] = h0;
            xr0 = xrN0; xz0 = xzN0; xn0 = xnN0;
            __syncwarp();                              // order lane pushes...
            if ((tid & 31) == 0) st_flag_release(p_flg0, su + 1);  // ...before flag
        }

        // ================= phase B: batch 1 (overlaps b0 transit) =================
        if (!own_half) {
            wait_flag(l_f10, su); wait_flag(l_f11, su); wait_flag(l_f12, su);
        }
        float xrN1 = 0.f, xzN1 = 0.f, xnN1 = 0.f;
        if (ks == 0) {
            const float* pn = proj + (size_t)ids_s[1][tn] * G3 + jg;
            xrN1 = __ldg(pn); xzN1 = __ldg(pn + H); xnN1 = __ldg(pn + 2 * H);
        }
        float sR1, sZ1, sN1;
        dot3(&hbuf[1][par][kslice * KC], wv, sR1, sZ1, sN1);
        if (ks != 0) {
            part[1][par][(ks - 1) * 3 + 0][jl] = sR1;
            part[1][par][(ks - 1) * 3 + 1][jl] = sZ1;
            part[1][par][(ks - 1) * 3 + 2][jl] = sN1;
        }
        __syncthreads();   // sync2 — b1 partials visible; hbuf[0][nxt](s) published

        if (ks == 0) {
            float aR = sR1 + part[1][par][0][jl] + part[1][par][3][jl] + part[1][par][6][jl];
            float aZ = sZ1 + part[1][par][1][jl] + part[1][par][4][jl] + part[1][par][7][jl];
            float aN = sN1 + part[1][par][2][jl] + part[1][par][5][jl] + part[1][par][8][jl];
            float r = sig_apx(xr1 + bhr + aR);
            float z = sig_apx(xz1 + bhz + aZ);
            float n = tanh_apx(fmaf(r, aN + bhn, xn1));
            h1 = fmaf(z, h1 - n, n);
            hbuf[1][nxt][jg] = h1;
            st_remote_f32(par ? r_h10 : r_h11, h1);
            allh1[(size_t)tcur * (2 * H)] = h1;
            xr1 = xrN1; xz1 = xzN1; xn1 = xnN1;
            __syncwarp();
            if ((tid & 31) == 0) st_flag_release(p_flg1, su + 1);
        }
        // dot_b0(s+1) own-half reads hbuf[0][nxt]: ordered by sync2(s).
        // dot_b1(s+1) own-half reads hbuf[1][nxt]: ordered by sync1(s+1).
        // Buffer reuse at s+2 is gated through two flag/sync round-trips.
    }

    cluster_barrier();   // no CTA exits while peer may still write into it
}

// ---------------- alignment no-op (keeps gru_kernel at absolute launch idx 3) ----------------
__global__ void nop_kernel() {}

// ---------------- kernel 3: gather (unchanged, verified) ----------------
__global__ void gather_kernel(const int* __restrict__ start_ids,
                              const int* __restrict__ end_ids,
                              float* __restrict__ out) {
    const int s = blockIdx.x, b = blockIdx.y;
    const int tid = threadIdx.x;  // 192 threads, 1 float4 each
    const int st = start_ids[(size_t)b * NSPAN + s];
    const int en = end_ids[(size_t)b * NSPAN + s];
    float4* orow = (float4*)(out + ((size_t)b * NSPAN + s) * 768);
    const float4* allh = (const float4*)g_allh;
    if (tid < 96) {
        orow[tid] = allh[((size_t)b * SEQL + st) * 96 + tid];
    } else {
        orow[tid] = allh[((size_t)b * SEQL + en) * 96 + (tid - 96)];
    }
}

// ---------------- launch ----------------
extern "C" void kernel_launch(void* const* d_in, const int* in_sizes, int n_in,
                              void* d_out, int out_size) {
    const int*   char_ids  = (const int*)d_in[0];
    const int*   start_ids = (const int*)d_in[1];
    const int*   end_ids   = (const int*)d_in[2];
    const float* emb       = (const float*)d_in[3];
    const float* w_ih_f    = (const float*)d_in[4];
    const float* w_hh_f    = (const float*)d_in[5];
    const float* b_ih_f    = (const float*)d_in[6];
    const float* b_hh_f    = (const float*)d_in[7];
    const float* w_ih_b    = (const float*)d_in[8];
    const float* w_hh_b    = (const float*)d_in[9];
    const float* b_ih_b    = (const float*)d_in[10];
    const float* b_hh_b    = (const float*)d_in[11];
    float* out = (float*)d_out;

    // launch order keeps absolute launch index 3 (the ncu-profiled one) = gru
    nop_kernel<<<1, 32>>>();

    // 1) projection tables: proj[d] = emb @ w_ih_d^T + b_ih_d  [1001, 576]
    proj_kernel<<<dim3((CHAR_VOCAB + VB - 1) / VB, 2), G3>>>(emb, w_ih_f, b_ih_f, w_ih_b, b_ih_b);

    nop_kernel<<<1, 32>>>();

    // 2) clustered bidirectional GRU: 2 batches per 2-CTA cluster, pipelined
    gru_kernel<<<dim3(2, 2, BATCH / 2), NTHR>>>(char_ids, w_hh_f, b_hh_f, w_hh_b, b_hh_b);

    // 3) gather start/end hidden states into output [32, 512, 768]
    gather_kernel<<<dim3(NSPAN, BATCH), 192>>>(start_ids, end_ids, out);
}

// round 17
// speedup vs baseline: 1.1949x; 1.1949x over previous
#include <cuda_runtime.h>
#include <cstdint>

#define CHAR_VOCAB 1001
#define EMB 256
#define H 192
#define G3 576   // 3*H
#define BATCH 32
#define SEQL 2048
#define NSPAN 512

// cluster split: 2 CTAs per recurrence, 6-way K split
#define JH 96            // outputs per CTA
#define KS 6             // K-split ways
#define KC 32            // K per slice
#define NTHR (JH * KS)   // 576 threads, 18 warps

// ---------------- scratch (no cudaMalloc allowed) ----------------
__device__ float g_proj[2][CHAR_VOCAB * G3];                 // 2 x 2.3 MB
__device__ float g_allh[(size_t)BATCH * SEQL * 2 * H];       // 100.7 MB

// ---------------- kernel 1: proj tables (unchanged, verified) ----------------
#define VB 16
__global__ void proj_kernel(const float* __restrict__ emb,
                            const float* __restrict__ w_ih_f, const float* __restrict__ b_ih_f,
                            const float* __restrict__ w_ih_b, const float* __restrict__ b_ih_b) {
    __shared__ float embs[VB][EMB];
    const int dir = blockIdx.y;
    const float* __restrict__ w  = dir ? w_ih_b : w_ih_f;
    const float* __restrict__ bi = dir ? b_ih_b : b_ih_f;
    const int v0 = blockIdx.x * VB;

    for (int i = threadIdx.x; i < VB * EMB; i += blockDim.x) {
        int v = v0 + i / EMB;
        embs[i / EMB][i % EMB] = (v < CHAR_VOCAB) ? emb[(size_t)v * EMB + (i % EMB)] : 0.f;
    }
    __syncthreads();

    const int g = threadIdx.x;  // 0..575
    float acc[VB];
#pragma unroll
    for (int i = 0; i < VB; i++) acc[i] = 0.f;

    const float4* __restrict__ w4 = (const float4*)(w + (size_t)g * EMB);
    for (int e4 = 0; e4 < EMB / 4; e4++) {
        float4 wv = w4[e4];
#pragma unroll
        for (int i = 0; i < VB; i++) {
            float4 ev = *(const float4*)&embs[i][e4 * 4];
            acc[i] = fmaf(wv.x, ev.x, fmaf(wv.y, ev.y, fmaf(wv.z, ev.z, fmaf(wv.w, ev.w, acc[i]))));
        }
    }
    float bb = bi[g];
#pragma unroll
    for (int i = 0; i < VB; i++) {
        int v = v0 + i;
        if (v < CHAR_VOCAB) g_proj[dir][(size_t)v * G3 + g] = acc[i] + bb;
    }
}

// ---------------- PTX helpers ----------------
__device__ __forceinline__ uint32_t smem_u32(const void* p) {
    uint32_t a;
    asm("{ .reg .u64 t; cvta.to.shared.u64 t, %1; cvt.u32.u64 %0, t; }" : "=r"(a) : "l"(p));
    return a;
}
__device__ __forceinline__ uint32_t mapa_u32(uint32_t laddr, uint32_t peer) {
    uint32_t r;
    asm("mapa.shared::cluster.u32 %0, %1, %2;" : "=r"(r) : "r"(laddr), "r"(peer));
    return r;
}
__device__ __forceinline__ void st_remote_f32(uint32_t raddr, float v) {
    asm volatile("st.shared::cluster.b32 [%0], %1;" :: "r"(raddr), "r"(__float_as_uint(v)) : "memory");
}
// release-store of a sequence flag into the PEER's smem (cluster scope)
__device__ __forceinline__ void st_flag_release(uint32_t raddr, uint32_t v) {
    asm volatile("st.release.cluster.shared::cluster.b32 [%0], %1;" :: "r"(raddr), "r"(v) : "memory");
}
// acquire-load poll of a LOCAL smem flag until flag >= target.
// Monotonic sequence numbers — producer run-ahead passes immediately, no
// parity aliasing, no deadlock window.
__device__ __forceinline__ void wait_flag(uint32_t laddr, uint32_t target) {
    uint32_t v;
    do {
        asm volatile("ld.acquire.cluster.shared::cta.b32 %0, [%1];"
                     : "=r"(v) : "r"(laddr) : "memory");
    } while ((int)v < (int)target);
}
__device__ __forceinline__ void cluster_barrier() {
    asm volatile("barrier.cluster.arrive.aligned;" ::: "memory");
    asm volatile("barrier.cluster.wait.aligned;" ::: "memory");
}

// single-MUFU tanh; sigmoid(x) = 0.5 + 0.5*tanh(x/2)
__device__ __forceinline__ float tanh_apx(float x) {
    float y; asm("tanh.approx.f32 %0, %1;" : "=f"(y) : "f"(x)); return y;
}
__device__ __forceinline__ float sig_apx(float x) {
    return fmaf(0.5f, tanh_apx(0.5f * x), 0.5f);
}
__device__ __forceinline__ uint32_t bf16rn(float f) {
    uint32_t u = __float_as_uint(f);
    return (u + 0x7FFFu + ((u >> 16) & 1u)) >> 16;
}

// one dual-MAC on a packed bf16 pair (known-good regalloc form)
#define DOT2(a0, a1, w, hx, hy) { \
    float wl = __uint_as_float((w) << 16); \
    float wh = __uint_as_float((w) & 0xFFFF0000u); \
    a0 = fmaf(wl, (hx), a0); a1 = fmaf(wh, (hy), a1); }

// 3-gate dot over this thread's 32-element K slice (16 packed pairs per gate)
__device__ __forceinline__ void dot3(const float* __restrict__ hb,
                                     const uint32_t wv[3][16],
                                     float& sR, float& sZ, float& sN) {
    float aR0 = 0.f, aR1 = 0.f, aZ0 = 0.f, aZ1 = 0.f, aN0 = 0.f, aN1 = 0.f;
#pragma unroll
    for (int q = 0; q < 8; q++) {
        float4 h4 = *(const float4*)(hb + 4 * q);
        DOT2(aR0, aR1, wv[0][2 * q],     h4.x, h4.y);
        DOT2(aR0, aR1, wv[0][2 * q + 1], h4.z, h4.w);
        DOT2(aZ0, aZ1, wv[1][2 * q],     h4.x, h4.y);
        DOT2(aZ0, aZ1, wv[1][2 * q + 1], h4.z, h4.w);
        DOT2(aN0, aN1, wv[2][2 * q],     h4.x, h4.y);
        DOT2(aN0, aN1, wv[2][2 * q + 1], h4.z, h4.w);
    }
    sR = aR0 + aR1; sZ = aZ0 + aZ1; sN = aN0 + aN1;
}

// ---------------- kernel 2: clustered GRU, KS=6 (18 warps for stall hiding) --
// cluster(2,1,1): rank r owns global j in [96r,96r+96). W_hh slice in REGISTERS
// (48 packed-bf16 u32/thread). 576 thr = (ks 0..5) x (jl 0..95); warp uniform ks.
// kslice = (ks + 3*rank) % 6: ks<3 consumes OWN half of h (handoff via named
// bar.sync(2,288)); ks>=3 consumes PEER half (polls 3 sequence flags, set by
// peer's ks0 warps with release-stores after pushing h).
__global__ void __launch_bounds__(NTHR, 1) __cluster_dims__(2, 1, 1)
gru_kernel(const int* __restrict__ char_ids,
           const float* __restrict__ w_hh_f, const float* __restrict__ b_hh_f,
           const float* __restrict__ w_hh_b, const float* __restrict__ b_hh_b) {
    __shared__ float hbuf[2][H];           // [parity][H], double-buffered full h
    __shared__ float part[2][15][JH];      // [parity][(ks-1)*3+gate][jl]
    __shared__ int   ids_s[SEQL];
    __shared__ uint32_t flg[4];            // producer warp 0..2 flags (+pad)

    const int rank = blockIdx.x;
    const int dir  = blockIdx.y;
    const int b    = blockIdx.z;
    const float* __restrict__ whh = dir ? w_hh_b : w_hh_f;
    const float* __restrict__ bhh = dir ? b_hh_b : b_hh_f;
    const float* __restrict__ proj = g_proj[dir];

    const int tid = threadIdx.x;
    const int ks  = tid / JH;                 // 0..5 (uniform per warp: 96=3*32)
    const int jl  = tid % JH;                 // 0..95
    const int jg  = rank * JH + jl;           // 0..191
    int kx = ks + 3 * rank;                   // kslice = (ks + 3*rank) % 6
    const int kslice = (kx >= 6) ? kx - 6 : kx;
    const bool own_half = (ks < 3);

    // ---- prologue ----
    if (tid < 4) flg[tid] = 0;                 // flags = 0 (step-0 input = zeros)
    if (tid < 2 * H) ((float*)hbuf)[tid] = 0.f;
    for (int t = tid; t < SEQL; t += NTHR) ids_s[t] = char_ids[(size_t)b * SEQL + t];

    // W_hh slice -> registers, packed bf16 pairs: wv[g][p] = (k=2p lo, k=2p+1 hi)
    uint32_t wv[3][16];
#pragma unroll
    for (int g = 0; g < 3; g++) {
        const float2* __restrict__ wr2 =
            (const float2*)(whh + ((size_t)(g * H + jg)) * H + kslice * KC);
#pragma unroll
        for (int q = 0; q < 16; q++) {
            float2 f = wr2[q];
            wv[g][q] = bf16rn(f.x) | (bf16rn(f.y) << 16);
        }
    }
    __syncthreads();
    cluster_barrier();   // zeroed flags + hbuf visible cluster-wide

    const uint32_t peer = rank ^ 1;
    const int wrp = tid >> 5;                  // producer warps are 0,1,2 (ks0)
    const uint32_t p_flg = mapa_u32(smem_u32(&flg[wrp & 3]), peer);
    const uint32_t l_f0 = smem_u32(&flg[0]);
    const uint32_t l_f1 = smem_u32(&flg[1]);
    const uint32_t l_f2 = smem_u32(&flg[2]);
    const uint32_t r_h0 = mapa_u32(smem_u32(&hbuf[0][jg]), peer);
    const uint32_t r_h1 = mapa_u32(smem_u32(&hbuf[1][jg]), peer);

    // ks0-only state
    float bhr = 0.f, bhz = 0.f, bhn = 0.f, h_j = 0.f;
    float xr = 0.f, xz = 0.f, xn = 0.f;
    float* allh_base = g_allh + ((size_t)b * SEQL) * (2 * H) + dir * H + jg;
    if (ks == 0) {
        bhr = bhh[jg]; bhz = bhh[H + jg]; bhn = bhh[2 * H + jg];
        int t0 = dir ? (SEQL - 1) : 0;
        const float* p0 = proj + (size_t)ids_s[t0] * G3 + jg;
        xr = p0[0]; xz = p0[H]; xn = p0[2 * H];
    }

#pragma unroll 1
    for (int s = 0; s < SEQL; s++) {
        const uint32_t par = (uint32_t)(s & 1);
        const int nxt = (s + 1) & 1;
        const uint32_t su = (uint32_t)s;

        // wait for this step's h slice
        if (own_half) {
            if (s > 0) asm volatile("bar.sync 2, 288;" ::: "memory"); // ks0..2
        } else {
            wait_flag(l_f0, su); wait_flag(l_f1, su); wait_flag(l_f2, su);
        }

        // prefetch next step's xp (ks0 only; latency hidden by the dot)
        float xrN = 0.f, xzN = 0.f, xnN = 0.f;
        if (ks == 0) {
            int sn = (s + 1 < SEQL) ? s + 1 : s;
            int tn = dir ? (SEQL - 1 - sn) : sn;
            const float* pn = proj + (size_t)ids_s[tn] * G3 + jg;
            xrN = __ldg(pn); xzN = __ldg(pn + H); xnN = __ldg(pn + 2 * H);
        }

        float sR, sZ, sN;
        dot3(&hbuf[par][kslice * KC], wv, sR, sZ, sN);
        if (ks != 0) {
            part[par][(ks - 1) * 3 + 0][jl] = sR;
            part[par][(ks - 1) * 3 + 1][jl] = sZ;
            part[par][(ks - 1) * 3 + 2][jl] = sN;
        }
        __syncthreads();   // partials visible; all local reads of hbuf[par] done

        if (ks == 0) {
            float aR = sR, aZ = sZ, aN = sN;
#pragma unroll
            for (int k = 0; k < 5; k++) {
                aR += part[par][k * 3 + 0][jl];
                aZ += part[par][k * 3 + 1][jl];
                aN += part[par][k * 3 + 2][jl];
            }
            float r = sig_apx(xr + bhr + aR);
            float z = sig_apx(xz + bhz + aZ);
            float n = tanh_apx(fmaf(r, aN + bhn, xn));
            h_j = fmaf(z, h_j - n, n);   // (1-z)*n + z*h

            hbuf[nxt][jg] = h_j;                       // local copy (own half)
            st_remote_f32(par ? r_h0 : r_h1, h_j);     // push into peer's copy
            int t = dir ? (SEQL - 1 - s) : s;
            allh_base[(size_t)t * (2 * H)] = h_j;
            xr = xrN; xz = xzN; xn = xnN;

            __syncwarp();                              // order lane pushes...
            if ((tid & 31) == 0) st_flag_release(p_flg, su + 1);  // ...before flag
        }
    }

    cluster_barrier();   // no CTA exits while peer may still write into it
}

// ---------------- alignment no-op (keeps gru_kernel at absolute launch idx 3) ----------------
__global__ void nop_kernel() {}

// ---------------- kernel 3: gather (unchanged, verified) ----------------
__global__ void gather_kernel(const int* __restrict__ start_ids,
                              const int* __restrict__ end_ids,
                              float* __restrict__ out) {
    const int s = blockIdx.x, b = blockIdx.y;
    const int tid = threadIdx.x;  // 192 threads, 1 float4 each
    const int st = start_ids[(size_t)b * NSPAN + s];
    const int en = end_ids[(size_t)b * NSPAN + s];
    float4* orow = (float4*)(out + ((size_t)b * NSPAN + s) * 768);
    const float4* allh = (const float4*)g_allh;
    if (tid < 96) {
        orow[tid] = allh[((size_t)b * SEQL + st) * 96 + tid];
    } else {
        orow[tid] = allh[((size_t)b * SEQL + en) * 96 + (tid - 96)];
    }
}

// ---------------- launch ----------------
extern "C" void kernel_launch(void* const* d_in, const int* in_sizes, int n_in,
                              void* d_out, int out_size) {
    const int*   char_ids  = (const int*)d_in[0];
    const int*   start_ids = (const int*)d_in[1];
    const int*   end_ids   = (const int*)d_in[2];
    const float* emb       = (const float*)d_in[3];
    const float* w_ih_f    = (const float*)d_in[4];
    const float* w_hh_f    = (const float*)d_in[5];
    const float* b_ih_f    = (const float*)d_in[6];
    const float* b_hh_f    = (const float*)d_in[7];
    const float* w_ih_b    = (const float*)d_in[8];
    const float* w_hh_b    = (const float*)d_in[9];
    const float* b_ih_b    = (const float*)d_in[10];
    const float* b_hh_b    = (const float*)d_in[11];
    float* out = (float*)d_out;

    // launch order keeps absolute launch index 3 (the ncu-profiled one) = gru
    nop_kernel<<<1, 32>>>();

    // 1) projection tables: proj[d] = emb @ w_ih_d^T + b_ih_d  [1001, 576]
    proj_kernel<<<dim3((CHAR_VOCAB + VB - 1) / VB, 2), G3>>>(emb, w_ih_f, b_ih_f, w_ih_b, b_ih_b);

    nop_kernel<<<1, 32>>>();

    // 2) clustered bidirectional GRU: 64 recurrences x 2-CTA clusters, 18 warps/CTA
    gru_kernel<<<dim3(2, 2, BATCH), NTHR>>>(char_ids, w_hh_f, b_hh_f, w_hh_b, b_hh_b);

    // 3) gather start/end hidden states into output [32, 512, 768]
    gather_kernel<<<dim3(NSPAN, BATCH), 192>>>(start_ids, end_ids, out);
}